// round 4
// baseline (speedup 1.0000x reference)
#include <cuda_runtime.h>
#include <cstdint>
#include <math.h>

// ---------------- problem constants ----------------
#define MTOK 2048
#define KDIM 2048
#define NDIM 1408
#define NEXP 8
#define CAP  1024
#define RROWS 4096
#define ECAP  8192

// ---------------- tiling ----------------
#define BM 128
#define BKT 16
#define SPAD 20              // 16 + 4 pad -> conflict-free mma fragment LDS
#define NTHR 256
#define BN1 64               // mlp1: 64 cols of gate AND 64 cols of up per CTA
#define BN2 128              // mlp2: 128 cols

// ---------------- scratch (device globals, allocation-free rule) ----------------
__device__ __align__(16) float g_act[(size_t)ECAP * NDIM];   // SwiGLU out (tf32-rounded); rows>=cnt stay 0
__device__ __align__(16) float g_dbuf[(size_t)ECAP * KDIM];  // down-proj output per slot
__device__ int g_cnt[NEXP];
__device__ int g_rowtok[ECAP];
__device__ int g_posmap[RROWS];

// ---------------- helpers ----------------
__device__ __forceinline__ float to_tf32(float x) {
    float r;
    asm("cvt.rna.tf32.f32 %0, %1;" : "=f"(r) : "f"(x));
    return r;
}
__device__ __forceinline__ float4 cvt4(float4 v) {
    v.x = to_tf32(v.x); v.y = to_tf32(v.y);
    v.z = to_tf32(v.z); v.w = to_tf32(v.w);
    return v;
}
__device__ __forceinline__ void mma8(float4& d, const uint32_t* a, const uint32_t* b) {
    asm volatile(
        "mma.sync.aligned.m16n8k8.row.col.f32.tf32.tf32.f32 "
        "{%0,%1,%2,%3}, {%4,%5,%6,%7}, {%8,%9}, {%0,%1,%2,%3};\n"
        : "+f"(d.x), "+f"(d.y), "+f"(d.z), "+f"(d.w)
        : "r"(a[0]), "r"(a[1]), "r"(a[2]), "r"(a[3]), "r"(b[0]), "r"(b[1]));
}

// ---------------- routing ----------------
__global__ void k_route(const int* __restrict__ idx) {
    __shared__ int sc[NEXP];
    const int tid = threadIdx.x;
    if (tid < NEXP) sc[tid] = 0;
    __syncthreads();
    for (int r = tid; r < RROWS; r += blockDim.x) {
        int e = idx[r];
        int slot = atomicAdd(&sc[e], 1);
        if (slot < CAP) {
            int p = e * CAP + slot;
            g_rowtok[p] = r >> 1;
            g_posmap[r] = p;
        } else {
            g_posmap[r] = e * CAP;
        }
    }
    __syncthreads();
    if (tid < NEXP) g_cnt[tid] = min(sc[tid], CAP);
}

// ---------------- activation ----------------
__device__ __forceinline__ float actf(float g, float u) {
    g = fminf(g, 10.0f);
    u = fminf(fmaxf(u, -10.0f), 10.0f);
    float s = g / (1.0f + expf(-g));
    return to_tf32(s * u);
}

// ---------------------------------------------------------------------------
// k_mlp1: fused gate+up GEMM (shared A tile) + SwiGLU epilogue -> g_act.
// CTA tile: 128 rows x 64 cols (for both gate and up). K = 2048, BKT=16.
// Warp layout: 2 (M) x 4 (N); warp tile 64 x 16 per output.
// ---------------------------------------------------------------------------
__global__ __launch_bounds__(NTHR, 2)
void k_mlp1(const float* __restrict__ H, const float* __restrict__ Wg,
            const float* __restrict__ Wu) {
    const int e    = blockIdx.z;
    const int cnt  = g_cnt[e];
    const int row0 = blockIdx.y * BM;
    if (row0 >= cnt) return;
    const int col0 = blockIdx.x * BN1;

    __shared__ __align__(16) float As[2][BM * SPAD];
    __shared__ __align__(16) float Bgs[2][BN1 * SPAD];
    __shared__ __align__(16) float Bus[2][BN1 * SPAD];

    const int tid  = threadIdx.x;
    const int lane = tid & 31;
    const int warp = tid >> 5;
    const int wm   = warp >> 2;      // 2 warps along M (64 rows each)
    const int wn   = warp & 3;       // 4 warps along N (16 cols each)
    const int grp  = lane >> 2;
    const int tig  = lane & 3;

    // A loader: 2 quads per thread (rows 0..63, 64..127)
    const int ar0 = tid >> 2;
    const int ak  = (tid & 3) * 4;
    const int ar1 = ar0 + 64;
    // B loader: 1 quad per thread per matrix (rows 0..63)
    const int br = tid >> 2;
    const int bk = ak;

    const bool av0 = (row0 + ar0) < cnt;
    const bool av1 = (row0 + ar1) < cnt;
    const float* ap0;
    const float* ap1;
    {
        int t0 = av0 ? g_rowtok[e * CAP + row0 + ar0] : 0;
        int t1 = av1 ? g_rowtok[e * CAP + row0 + ar1] : 0;
        ap0 = H + (size_t)t0 * KDIM + ak;
        ap1 = H + (size_t)t1 * KDIM + ak;
    }
    const size_t wbo = (size_t)e * NDIM * KDIM + (size_t)(col0 + br) * KDIM + bk;
    const float* bgp = Wg + wbo;
    const float* bup = Wu + wbo;

    float4 accg[4][2], accu[4][2];
#pragma unroll
    for (int i = 0; i < 4; ++i)
#pragma unroll
        for (int j = 0; j < 2; ++j) {
            accg[i][j] = make_float4(0.f, 0.f, 0.f, 0.f);
            accu[i][j] = make_float4(0.f, 0.f, 0.f, 0.f);
        }

    // Prologue: stage 0
    {
        float4 pa0 = make_float4(0.f, 0.f, 0.f, 0.f), pa1 = pa0;
        if (av0) pa0 = *(const float4*)ap0;
        if (av1) pa1 = *(const float4*)ap1;
        float4 pg = *(const float4*)bgp;
        float4 pu = *(const float4*)bup;
        *(float4*)&As[0][ar0 * SPAD + ak] = cvt4(pa0);
        *(float4*)&As[0][ar1 * SPAD + ak] = cvt4(pa1);
        *(float4*)&Bgs[0][br * SPAD + bk] = cvt4(pg);
        *(float4*)&Bus[0][br * SPAD + bk] = cvt4(pu);
    }
    __syncthreads();

    const int KT = KDIM / BKT;   // 128
    int buf = 0;
#pragma unroll 1
    for (int kt = 0; kt < KT; ++kt) {
        float4 na0, na1, ng, nu;
        const bool more = (kt + 1) < KT;
        if (more) {
            const int ko = (kt + 1) * BKT;
            na0 = make_float4(0.f, 0.f, 0.f, 0.f); na1 = na0;
            if (av0) na0 = *(const float4*)(ap0 + ko);
            if (av1) na1 = *(const float4*)(ap1 + ko);
            ng = *(const float4*)(bgp + ko);
            nu = *(const float4*)(bup + ko);
        }

#pragma unroll
        for (int ks = 0; ks < BKT; ks += 8) {
            uint32_t af[4][4], bgf[2][2], buf_[2][2];
#pragma unroll
            for (int mt = 0; mt < 4; ++mt) {
                const int rb = wm * 64 + mt * 16;
                const float* s = &As[buf][0];
                af[mt][0] = __float_as_uint(s[(rb + grp    ) * SPAD + ks + tig    ]);
                af[mt][1] = __float_as_uint(s[(rb + grp + 8) * SPAD + ks + tig    ]);
                af[mt][2] = __float_as_uint(s[(rb + grp    ) * SPAD + ks + tig + 4]);
                af[mt][3] = __float_as_uint(s[(rb + grp + 8) * SPAD + ks + tig + 4]);
            }
#pragma unroll
            for (int nt = 0; nt < 2; ++nt) {
                const int cb = wn * 16 + nt * 8;
                bgf[nt][0] = __float_as_uint(Bgs[buf][(cb + grp) * SPAD + ks + tig    ]);
                bgf[nt][1] = __float_as_uint(Bgs[buf][(cb + grp) * SPAD + ks + tig + 4]);
                buf_[nt][0] = __float_as_uint(Bus[buf][(cb + grp) * SPAD + ks + tig    ]);
                buf_[nt][1] = __float_as_uint(Bus[buf][(cb + grp) * SPAD + ks + tig + 4]);
            }
#pragma unroll
            for (int mt = 0; mt < 4; ++mt)
#pragma unroll
                for (int nt = 0; nt < 2; ++nt) {
                    mma8(accg[mt][nt], af[mt], bgf[nt]);
                    mma8(accu[mt][nt], af[mt], buf_[nt]);
                }
        }

        if (more) {
            const int nb = buf ^ 1;
            *(float4*)&As[nb][ar0 * SPAD + ak] = cvt4(na0);
            *(float4*)&As[nb][ar1 * SPAD + ak] = cvt4(na1);
            *(float4*)&Bgs[nb][br * SPAD + bk] = cvt4(ng);
            *(float4*)&Bus[nb][br * SPAD + bk] = cvt4(nu);
        }
        __syncthreads();
        buf ^= 1;
    }

    // Fused SwiGLU epilogue -> g_act (tf32-rounded). Rows >= cnt never written
    // (they remain zero from module init, which mlp2 relies on).
#pragma unroll
    for (int mt = 0; mt < 4; ++mt) {
        const int r0 = row0 + wm * 64 + mt * 16 + grp;
        const int r1 = r0 + 8;
#pragma unroll
        for (int nt = 0; nt < 2; ++nt) {
            const int c = col0 + wn * 16 + nt * 8 + tig * 2;
            float4 g = accg[mt][nt];
            float4 u = accu[mt][nt];
            if (r0 < cnt) {
                float* p = g_act + (size_t)(e * CAP + r0) * NDIM + c;
                *(float2*)p = make_float2(actf(g.x, u.x), actf(g.y, u.y));
            }
            if (r1 < cnt) {
                float* p = g_act + (size_t)(e * CAP + r1) * NDIM + c;
                *(float2*)p = make_float2(actf(g.z, u.z), actf(g.w, u.w));
            }
        }
    }
}

// ---------------------------------------------------------------------------
// k_mlp2: down-projection. A = g_act (already tf32-rounded, rows>=cnt are 0),
// B = down_weight. CTA tile 128 x 128, K = 1408.
// ---------------------------------------------------------------------------
__global__ __launch_bounds__(NTHR, 2)
void k_mlp2(const float* __restrict__ W) {
    const int e    = blockIdx.z;
    const int cnt  = g_cnt[e];
    const int row0 = blockIdx.y * BM;
    if (row0 >= cnt) return;
    const int col0 = blockIdx.x * BN2;

    __shared__ __align__(16) float As[2][BM * SPAD];
    __shared__ __align__(16) float Bs[2][BM * SPAD];

    const int tid  = threadIdx.x;
    const int lane = tid & 31;
    const int warp = tid >> 5;
    const int wm   = warp >> 2;
    const int wn   = warp & 3;
    const int grp  = lane >> 2;
    const int tig  = lane & 3;

    const int ar0 = tid >> 2;
    const int ak  = (tid & 3) * 4;
    const int ar1 = ar0 + 64;

    const float* ap0 = g_act + (size_t)(e * CAP + row0 + ar0) * NDIM + ak;
    const float* ap1 = g_act + (size_t)(e * CAP + row0 + ar1) * NDIM + ak;
    const float* bp0 = W + (size_t)e * KDIM * NDIM + (size_t)(col0 + ar0) * NDIM + ak;
    const float* bp1 = W + (size_t)e * KDIM * NDIM + (size_t)(col0 + ar1) * NDIM + ak;

    float4 acc[4][4];
#pragma unroll
    for (int i = 0; i < 4; ++i)
#pragma unroll
        for (int j = 0; j < 4; ++j) acc[i][j] = make_float4(0.f, 0.f, 0.f, 0.f);

    {
        float4 pa0 = *(const float4*)ap0;
        float4 pa1 = *(const float4*)ap1;
        float4 pb0 = *(const float4*)bp0;
        float4 pb1 = *(const float4*)bp1;
        *(float4*)&As[0][ar0 * SPAD + ak] = pa0;          // A pre-rounded: no cvt
        *(float4*)&As[0][ar1 * SPAD + ak] = pa1;
        *(float4*)&Bs[0][ar0 * SPAD + ak] = cvt4(pb0);
        *(float4*)&Bs[0][ar1 * SPAD + ak] = cvt4(pb1);
    }
    __syncthreads();

    const int KT = NDIM / BKT;   // 88
    int buf = 0;
#pragma unroll 1
    for (int kt = 0; kt < KT; ++kt) {
        float4 na0, na1, nb0, nb1;
        const bool more = (kt + 1) < KT;
        if (more) {
            const int ko = (kt + 1) * BKT;
            na0 = *(const float4*)(ap0 + ko);
            na1 = *(const float4*)(ap1 + ko);
            nb0 = *(const float4*)(bp0 + ko);
            nb1 = *(const float4*)(bp1 + ko);
        }

#pragma unroll
        for (int ks = 0; ks < BKT; ks += 8) {
            uint32_t af[4][4], bf[4][2];
#pragma unroll
            for (int mt = 0; mt < 4; ++mt) {
                const int rb = wm * 64 + mt * 16;
                const float* s = &As[buf][0];
                af[mt][0] = __float_as_uint(s[(rb + grp    ) * SPAD + ks + tig    ]);
                af[mt][1] = __float_as_uint(s[(rb + grp + 8) * SPAD + ks + tig    ]);
                af[mt][2] = __float_as_uint(s[(rb + grp    ) * SPAD + ks + tig + 4]);
                af[mt][3] = __float_as_uint(s[(rb + grp + 8) * SPAD + ks + tig + 4]);
            }
#pragma unroll
            for (int nt = 0; nt < 4; ++nt) {
                const int cb = wn * 32 + nt * 8;
                const float* s = &Bs[buf][0];
                bf[nt][0] = __float_as_uint(s[(cb + grp) * SPAD + ks + tig    ]);
                bf[nt][1] = __float_as_uint(s[(cb + grp) * SPAD + ks + tig + 4]);
            }
#pragma unroll
            for (int mt = 0; mt < 4; ++mt)
#pragma unroll
                for (int nt = 0; nt < 4; ++nt)
                    mma8(acc[mt][nt], af[mt], bf[nt]);
        }

        if (more) {
            const int nb = buf ^ 1;
            *(float4*)&As[nb][ar0 * SPAD + ak] = na0;
            *(float4*)&As[nb][ar1 * SPAD + ak] = na1;
            *(float4*)&Bs[nb][ar0 * SPAD + ak] = cvt4(nb0);
            *(float4*)&Bs[nb][ar1 * SPAD + ak] = cvt4(nb1);
        }
        __syncthreads();
        buf ^= 1;
    }

#pragma unroll
    for (int mt = 0; mt < 4; ++mt) {
        const int r0 = row0 + wm * 64 + mt * 16 + grp;
        const int r1 = r0 + 8;
#pragma unroll
        for (int nt = 0; nt < 4; ++nt) {
            const int c = col0 + wn * 32 + nt * 8 + tig * 2;
            float4 v = acc[mt][nt];
            if (r0 < cnt) *(float2*)&g_dbuf[(size_t)(e * CAP + r0) * KDIM + c] = make_float2(v.x, v.y);
            if (r1 < cnt) *(float2*)&g_dbuf[(size_t)(e * CAP + r1) * KDIM + c] = make_float2(v.z, v.w);
        }
    }
}

// ---------------- combine ----------------
__global__ void k_combine(const float* __restrict__ gate, float* __restrict__ out) {
    const int t = blockIdx.x;
    const int p0 = g_posmap[2 * t];
    const int p1 = g_posmap[2 * t + 1];
    const float g0 = gate[2 * t];
    const float g1 = gate[2 * t + 1];
    const float4* d0 = (const float4*)(g_dbuf + (size_t)p0 * KDIM);
    const float4* d1 = (const float4*)(g_dbuf + (size_t)p1 * KDIM);
    float4* o = (float4*)(out + (size_t)t * KDIM);
    for (int i = threadIdx.x; i < KDIM / 4; i += blockDim.x) {
        float4 a = d0[i];
        float4 b = d1[i];
        o[i] = make_float4(g0 * a.x + g1 * b.x, g0 * a.y + g1 * b.y,
                           g0 * a.z + g1 * b.z, g0 * a.w + g1 * b.w);
    }
}

extern "C" void kernel_launch(void* const* d_in, const int* in_sizes, int n_in,
                              void* d_out, int out_size) {
    (void)in_sizes; (void)n_in; (void)out_size;
    const float* flat_h    = (const float*)d_in[0];
    const int*   flat_idx  = (const int*)  d_in[1];
    const float* flat_gate = (const float*)d_in[2];
    const float* gate_w    = (const float*)d_in[3];
    const float* up_w      = (const float*)d_in[4];
    const float* down_w    = (const float*)d_in[5];
    float* out = (float*)d_out;

    k_route<<<1, 256>>>(flat_idx);

    dim3 grid1(NDIM / BN1, CAP / BM, NEXP);   // (22, 8, 8)
    k_mlp1<<<grid1, NTHR>>>(flat_h, gate_w, up_w);

    dim3 grid2(KDIM / BN2, CAP / BM, NEXP);   // (16, 8, 8)
    k_mlp2<<<grid2, NTHR>>>(down_w);

    k_combine<<<MTOK, 256>>>(flat_gate, out);
}

// round 5
// speedup vs baseline: 1.4162x; 1.4162x over previous
#include <cuda_runtime.h>
#include <cstdint>
#include <math.h>

// ---------------- problem constants ----------------
#define MTOK 2048
#define KDIM 2048
#define NDIM 1408
#define NEXP 8
#define CAP  1024
#define RROWS 4096
#define ECAP  8192

// ---------------- tiling ----------------
#define BM 256
#define BN 128
#define BKT 16
#define SPAD 20              // 16 + 4 pad -> conflict-free mma fragment LDS
#define NTHR 512

#define SMEM_BYTES ((2 * BM * SPAD + 2 * BN * SPAD) * 4)   // 61440

// ---------------- scratch (device globals, allocation-free rule) ----------------
__device__ __align__(16) float g_gbuf[(size_t)ECAP * NDIM]; // gate pre-activation
__device__ __align__(16) float g_act[(size_t)ECAP * NDIM];  // SwiGLU out (tf32-rounded); rows>=cnt stay 0
__device__ __align__(16) float g_dbuf[(size_t)ECAP * KDIM]; // down-proj output per slot
__device__ int g_cnt[NEXP];
__device__ int g_rowtok[ECAP];
__device__ int g_posmap[RROWS];

// ---------------- helpers ----------------
__device__ __forceinline__ float to_tf32(float x) {
    float r;
    asm("cvt.rna.tf32.f32 %0, %1;" : "=f"(r) : "f"(x));
    return r;
}
__device__ __forceinline__ float4 cvt4(float4 v) {
    v.x = to_tf32(v.x); v.y = to_tf32(v.y);
    v.z = to_tf32(v.z); v.w = to_tf32(v.w);
    return v;
}
__device__ __forceinline__ void mma8(float4& d, const uint32_t* a, const uint32_t* b) {
    asm volatile(
        "mma.sync.aligned.m16n8k8.row.col.f32.tf32.tf32.f32 "
        "{%0,%1,%2,%3}, {%4,%5,%6,%7}, {%8,%9}, {%0,%1,%2,%3};\n"
        : "+f"(d.x), "+f"(d.y), "+f"(d.z), "+f"(d.w)
        : "r"(a[0]), "r"(a[1]), "r"(a[2]), "r"(a[3]), "r"(b[0]), "r"(b[1]));
}

// ---------------- routing ----------------
__global__ void k_route(const int* __restrict__ idx) {
    __shared__ int sc[NEXP];
    const int tid = threadIdx.x;
    if (tid < NEXP) sc[tid] = 0;
    __syncthreads();
    for (int r = tid; r < RROWS; r += blockDim.x) {
        int e = idx[r];
        int slot = atomicAdd(&sc[e], 1);
        if (slot < CAP) {
            int p = e * CAP + slot;
            g_rowtok[p] = r >> 1;
            g_posmap[r] = p;
        } else {
            g_posmap[r] = e * CAP;
        }
    }
    __syncthreads();
    if (tid < NEXP) g_cnt[tid] = min(sc[tid], CAP);
}

// ---------------- activation ----------------
__device__ __forceinline__ float actf(float g, float u) {
    g = fminf(g, 10.0f);
    u = fminf(fmaxf(u, -10.0f), 10.0f);
    float s = g / (1.0f + expf(-g));
    return to_tf32(s * u);
}

// ---------------------------------------------------------------------------
// Grouped NT GEMM, tile 256(M) x 128(N), 512 threads, double-buffered smem.
//   SRC 0: A gathered from flat_h (cvt to tf32), KD=2048
//   SRC 1: A from g_act (pre-rounded, no cvt),   KD=1408
//   OUT 0: write raw acc -> g_gbuf   (gate pre-act)
//   OUT 1: SwiGLU epilogue: read g_gbuf, acc=u -> g_act (tf32-rounded)
//   OUT 2: write raw acc -> g_dbuf
// Warp layout: 16 warps = 4(M) x 4(N); warp tile 64 x 32.
// ---------------------------------------------------------------------------
template<int KD, int SRC, int OUT>
__global__ __launch_bounds__(NTHR, 1)
void k_gemm(const float* __restrict__ Ain, const float* __restrict__ B) {
    extern __shared__ __align__(16) float smem[];
    float* As = smem;                       // 2 stages of BM x SPAD
    float* Bs = smem + 2 * BM * SPAD;       // 2 stages of BN x SPAD

    const int e    = blockIdx.z;
    const int cnt  = g_cnt[e];
    const int row0 = blockIdx.y * BM;
    if (row0 >= cnt) return;
    const int col0 = blockIdx.x * BN;

    const int tid  = threadIdx.x;
    const int lane = tid & 31;
    const int warp = tid >> 5;
    const int wm   = warp >> 2;      // 0..3, 64 rows each
    const int wn   = warp & 3;       // 0..3, 32 cols each
    const int grp  = lane >> 2;
    const int tig  = lane & 3;

    // A loader: 2 float4/thread (rows 0..127, 128..255)
    const int ar0 = tid >> 2;            // 0..127
    const int ak  = (tid & 3) * 4;
    const int ar1 = ar0 + 128;
    // B loader: 1 float4/thread (rows 0..127)
    const int br = ar0;

    const float* ap0;
    const float* ap1;
    bool av0, av1;
    if (SRC == 0) {
        av0 = (row0 + ar0) < cnt;
        av1 = (row0 + ar1) < cnt;
        int t0 = av0 ? g_rowtok[e * CAP + row0 + ar0] : 0;
        int t1 = av1 ? g_rowtok[e * CAP + row0 + ar1] : 0;
        ap0 = Ain + (size_t)t0 * KD + ak;
        ap1 = Ain + (size_t)t1 * KD + ak;
    } else {
        av0 = av1 = true;                 // g_act rows >= cnt are zero
        ap0 = g_act + (size_t)(e * CAP + row0 + ar0) * KD + ak;
        ap1 = g_act + (size_t)(e * CAP + row0 + ar1) * KD + ak;
    }
    const float* bp = B + (size_t)e * ((size_t)NDIM * KDIM) + (size_t)(col0 + br) * KD + ak;

    float4 acc[4][4];
#pragma unroll
    for (int i = 0; i < 4; ++i)
#pragma unroll
        for (int j = 0; j < 4; ++j) acc[i][j] = make_float4(0.f, 0.f, 0.f, 0.f);

    // Prologue: stage 0
    {
        float4 pa0 = make_float4(0.f, 0.f, 0.f, 0.f), pa1 = pa0;
        if (av0) pa0 = *(const float4*)ap0;
        if (av1) pa1 = *(const float4*)ap1;
        float4 pb = *(const float4*)bp;
        if (SRC == 0) { pa0 = cvt4(pa0); pa1 = cvt4(pa1); }
        *(float4*)&As[ar0 * SPAD + ak] = pa0;
        *(float4*)&As[ar1 * SPAD + ak] = pa1;
        *(float4*)&Bs[br * SPAD + ak] = cvt4(pb);
    }
    __syncthreads();

    const int KT = KD / BKT;
    int buf = 0;
#pragma unroll 1
    for (int kt = 0; kt < KT; ++kt) {
        float4 na0, na1, nb;
        const bool more = (kt + 1) < KT;
        if (more) {
            const int ko = (kt + 1) * BKT;
            na0 = make_float4(0.f, 0.f, 0.f, 0.f); na1 = na0;
            if (av0) na0 = *(const float4*)(ap0 + ko);
            if (av1) na1 = *(const float4*)(ap1 + ko);
            nb = *(const float4*)(bp + ko);
        }

        const float* as = As + buf * (BM * SPAD);
        const float* bs = Bs + buf * (BN * SPAD);
#pragma unroll
        for (int ks = 0; ks < BKT; ks += 8) {
            uint32_t af[4][4], bf[4][2];
#pragma unroll
            for (int mt = 0; mt < 4; ++mt) {
                const int rb = wm * 64 + mt * 16;
                af[mt][0] = __float_as_uint(as[(rb + grp    ) * SPAD + ks + tig    ]);
                af[mt][1] = __float_as_uint(as[(rb + grp + 8) * SPAD + ks + tig    ]);
                af[mt][2] = __float_as_uint(as[(rb + grp    ) * SPAD + ks + tig + 4]);
                af[mt][3] = __float_as_uint(as[(rb + grp + 8) * SPAD + ks + tig + 4]);
            }
#pragma unroll
            for (int nt = 0; nt < 4; ++nt) {
                const int cb = wn * 32 + nt * 8;
                bf[nt][0] = __float_as_uint(bs[(cb + grp) * SPAD + ks + tig    ]);
                bf[nt][1] = __float_as_uint(bs[(cb + grp) * SPAD + ks + tig + 4]);
            }
#pragma unroll
            for (int mt = 0; mt < 4; ++mt)
#pragma unroll
                for (int nt = 0; nt < 4; ++nt)
                    mma8(acc[mt][nt], af[mt], bf[nt]);
        }

        if (more) {
            float* asn = As + (buf ^ 1) * (BM * SPAD);
            float* bsn = Bs + (buf ^ 1) * (BN * SPAD);
            if (SRC == 0) { na0 = cvt4(na0); na1 = cvt4(na1); }
            *(float4*)&asn[ar0 * SPAD + ak] = na0;
            *(float4*)&asn[ar1 * SPAD + ak] = na1;
            *(float4*)&bsn[br * SPAD + ak] = cvt4(nb);
        }
        __syncthreads();
        buf ^= 1;
    }

    // Epilogue
#pragma unroll
    for (int mt = 0; mt < 4; ++mt) {
        const int r0 = row0 + wm * 64 + mt * 16 + grp;
        const int r1 = r0 + 8;
#pragma unroll
        for (int nt = 0; nt < 4; ++nt) {
            const int c = col0 + wn * 32 + nt * 8 + tig * 2;
            float4 v = acc[mt][nt];
            if (OUT == 0) {
                if (r0 < cnt) *(float2*)&g_gbuf[(size_t)(e * CAP + r0) * NDIM + c] = make_float2(v.x, v.y);
                if (r1 < cnt) *(float2*)&g_gbuf[(size_t)(e * CAP + r1) * NDIM + c] = make_float2(v.z, v.w);
            } else if (OUT == 1) {
                if (r0 < cnt) {
                    const size_t o = (size_t)(e * CAP + r0) * NDIM + c;
                    float2 g = *(const float2*)&g_gbuf[o];
                    *(float2*)&g_act[o] = make_float2(actf(g.x, v.x), actf(g.y, v.y));
                }
                if (r1 < cnt) {
                    const size_t o = (size_t)(e * CAP + r1) * NDIM + c;
                    float2 g = *(const float2*)&g_gbuf[o];
                    *(float2*)&g_act[o] = make_float2(actf(g.x, v.z), actf(g.y, v.w));
                }
            } else {
                if (r0 < cnt) *(float2*)&g_dbuf[(size_t)(e * CAP + r0) * KDIM + c] = make_float2(v.x, v.y);
                if (r1 < cnt) *(float2*)&g_dbuf[(size_t)(e * CAP + r1) * KDIM + c] = make_float2(v.z, v.w);
            }
        }
    }
}

// ---------------- combine ----------------
__global__ void k_combine(const float* __restrict__ gate, float* __restrict__ out) {
    const int t = blockIdx.x;
    const int p0 = g_posmap[2 * t];
    const int p1 = g_posmap[2 * t + 1];
    const float g0 = gate[2 * t];
    const float g1 = gate[2 * t + 1];
    const float4* d0 = (const float4*)(g_dbuf + (size_t)p0 * KDIM);
    const float4* d1 = (const float4*)(g_dbuf + (size_t)p1 * KDIM);
    float4* o = (float4*)(out + (size_t)t * KDIM);
    for (int i = threadIdx.x; i < KDIM / 4; i += blockDim.x) {
        float4 a = d0[i];
        float4 b = d1[i];
        o[i] = make_float4(g0 * a.x + g1 * b.x, g0 * a.y + g1 * b.y,
                           g0 * a.z + g1 * b.z, g0 * a.w + g1 * b.w);
    }
}

extern "C" void kernel_launch(void* const* d_in, const int* in_sizes, int n_in,
                              void* d_out, int out_size) {
    (void)in_sizes; (void)n_in; (void)out_size;
    const float* flat_h    = (const float*)d_in[0];
    const int*   flat_idx  = (const int*)  d_in[1];
    const float* flat_gate = (const float*)d_in[2];
    const float* gate_w    = (const float*)d_in[3];
    const float* up_w      = (const float*)d_in[4];
    const float* down_w    = (const float*)d_in[5];
    float* out = (float*)d_out;

    cudaFuncSetAttribute(k_gemm<KDIM, 0, 0>, cudaFuncAttributeMaxDynamicSharedMemorySize, SMEM_BYTES);
    cudaFuncSetAttribute(k_gemm<KDIM, 0, 1>, cudaFuncAttributeMaxDynamicSharedMemorySize, SMEM_BYTES);
    cudaFuncSetAttribute(k_gemm<NDIM, 1, 2>, cudaFuncAttributeMaxDynamicSharedMemorySize, SMEM_BYTES);

    k_route<<<1, 256>>>(flat_idx);

    dim3 grid1(NDIM / BN, CAP / BM, NEXP);   // (11, 4, 8)
    k_gemm<KDIM, 0, 0><<<grid1, NTHR, SMEM_BYTES>>>(flat_h, gate_w);   // gate pre-act
    k_gemm<KDIM, 0, 1><<<grid1, NTHR, SMEM_BYTES>>>(flat_h, up_w);     // up + SwiGLU

    dim3 grid2(KDIM / BN, CAP / BM, NEXP);   // (16, 4, 8)
    k_gemm<NDIM, 1, 2><<<grid2, NTHR, SMEM_BYTES>>>(nullptr, down_w);  // down

    k_combine<<<MTOK, 256>>>(flat_gate, out);
}

// round 7
// speedup vs baseline: 1.7832x; 1.2591x over previous
#include <cuda_runtime.h>
#include <cstdint>
#include <math.h>

// ---------------- problem constants ----------------
#define MTOK 2048
#define KDIM 2048
#define NDIM 1408
#define NEXP 8
#define CAP  1024
#define RROWS 4096
#define ECAP  8192

// ---------------- tiling ----------------
#define BM 128
#define BN 128
#define BKT 16
#define SPAD 20              // 80-byte row stride: LDSM row-addresses cover all 32 banks
#define NTHR 256
#define ABYTES (BM * SPAD * 4)   // one A stage in bytes
#define BBYTES (BN * SPAD * 4)

// ---------------- scratch (device globals, allocation-free rule) ----------------
__device__ __align__(16) float g_gbuf[(size_t)ECAP * NDIM]; // gate pre-activation
__device__ __align__(16) float g_act[(size_t)ECAP * NDIM];  // SwiGLU out (tf32-rounded); rows>=cnt stay 0
__device__ __align__(16) float g_dbuf[(size_t)ECAP * KDIM]; // down-proj output per slot
__device__ int g_cnt[NEXP];
__device__ int g_rowtok[ECAP];
__device__ int g_posmap[RROWS];

// ---------------- helpers ----------------
__device__ __forceinline__ float to_tf32(float x) {
    float r;
    asm("cvt.rna.tf32.f32 %0, %1;" : "=f"(r) : "f"(x));
    return r;
}
__device__ __forceinline__ float4 cvt4(float4 v) {
    v.x = to_tf32(v.x); v.y = to_tf32(v.y);
    v.z = to_tf32(v.z); v.w = to_tf32(v.w);
    return v;
}
__device__ __forceinline__ void mma8(float4& d, const uint32_t* a, const uint32_t* b) {
    asm volatile(
        "mma.sync.aligned.m16n8k8.row.col.f32.tf32.tf32.f32 "
        "{%0,%1,%2,%3}, {%4,%5,%6,%7}, {%8,%9}, {%0,%1,%2,%3};\n"
        : "+f"(d.x), "+f"(d.y), "+f"(d.z), "+f"(d.w)
        : "r"(a[0]), "r"(a[1]), "r"(a[2]), "r"(a[3]), "r"(b[0]), "r"(b[1]));
}
// tf32 A fragment (a0..a3) == ldmatrix.x4.b16 of [rows rb..rb+15] x [k ks..ks+7]
__device__ __forceinline__ void ldsm_x4(uint32_t* a, uint32_t addr) {
    asm volatile("ldmatrix.sync.aligned.m8n8.x4.shared.b16 {%0,%1,%2,%3}, [%4];"
                 : "=r"(a[0]), "=r"(a[1]), "=r"(a[2]), "=r"(a[3]) : "r"(addr));
}
// tf32 B fragment (b0,b1) == ldmatrix.x2.b16 of [n-rows cb..cb+7] x [k ks..ks+7]
__device__ __forceinline__ void ldsm_x2(uint32_t* b, uint32_t addr) {
    asm volatile("ldmatrix.sync.aligned.m8n8.x2.shared.b16 {%0,%1}, [%2];"
                 : "=r"(b[0]), "=r"(b[1]) : "r"(addr));
}

// ---------------- routing ----------------
__global__ void k_route(const int* __restrict__ idx) {
    __shared__ int sc[NEXP];
    const int tid = threadIdx.x;
    if (tid < NEXP) sc[tid] = 0;
    __syncthreads();
    for (int r = tid; r < RROWS; r += blockDim.x) {
        int e = idx[r];
        int slot = atomicAdd(&sc[e], 1);
        if (slot < CAP) {
            int p = e * CAP + slot;
            g_rowtok[p] = r >> 1;
            g_posmap[r] = p;
        } else {
            g_posmap[r] = e * CAP;
        }
    }
    __syncthreads();
    if (tid < NEXP) g_cnt[tid] = min(sc[tid], CAP);
}

// ---------------- activation ----------------
__device__ __forceinline__ float actf(float g, float u) {
    g = fminf(g, 10.0f);
    u = fminf(fmaxf(u, -10.0f), 10.0f);
    float s = g / (1.0f + expf(-g));
    return to_tf32(s * u);
}

// ---------------------------------------------------------------------------
// Grouped NT GEMM, tile 128x128, 256 threads, occ 2, double-buffered smem,
// ldmatrix fragment loads.
//   SRC 0: A gathered from flat_h (cvt tf32), KD=2048
//   SRC 1: A from g_act (pre-rounded, rows>=cnt zero), KD=1408
//   OUT 0: raw acc -> g_gbuf (gate pre-act)
//   OUT 1: SwiGLU: read g_gbuf, acc=u -> g_act (tf32-rounded)
//   OUT 2: raw acc -> g_dbuf
// Warp layout: 8 warps = 2(M) x 4(N); warp tile 64x32.
// ---------------------------------------------------------------------------
template<int KD, int SRC, int OUT>
__global__ __launch_bounds__(NTHR, 2)
void k_gemm(const float* __restrict__ Ain, const float* __restrict__ B) {
    __shared__ __align__(16) float As[2][BM * SPAD];
    __shared__ __align__(16) float Bs[2][BN * SPAD];

    const int e    = blockIdx.z;
    const int cnt  = g_cnt[e];
    const int row0 = blockIdx.y * BM;
    if (row0 >= cnt) return;
    const int col0 = blockIdx.x * BN;

    const int tid  = threadIdx.x;
    const int lane = tid & 31;
    const int warp = tid >> 5;
    const int wm   = warp >> 2;      // 2 warps along M
    const int wn   = warp & 3;       // 4 warps along N
    const int grp  = lane >> 2;
    const int tig  = lane & 3;

    // Loader: 2 float4 quads each for A and B per stage
    const int ar0 = tid >> 2;            // 0..63
    const int ak  = (tid & 3) * 4;
    const int ar1 = ar0 + 64;

    const float* ap0;
    const float* ap1;
    bool av0, av1;
    if (SRC == 0) {
        av0 = (row0 + ar0) < cnt;
        av1 = (row0 + ar1) < cnt;
        int t0 = av0 ? g_rowtok[e * CAP + row0 + ar0] : 0;
        int t1 = av1 ? g_rowtok[e * CAP + row0 + ar1] : 0;
        ap0 = Ain + (size_t)t0 * KD + ak;
        ap1 = Ain + (size_t)t1 * KD + ak;
    } else {
        av0 = av1 = true;
        ap0 = g_act + (size_t)(e * CAP + row0 + ar0) * KD + ak;
        ap1 = g_act + (size_t)(e * CAP + row0 + ar1) * KD + ak;
    }
    const float* bp0 = B + (size_t)e * ((size_t)NDIM * KDIM) + (size_t)(col0 + ar0) * KD + ak;
    const float* bp1 = B + (size_t)e * ((size_t)NDIM * KDIM) + (size_t)(col0 + ar1) * KD + ak;

    // ldmatrix lane-address bases (byte offsets in shared space)
    const uint32_t sA = (uint32_t)__cvta_generic_to_shared(As);
    const uint32_t sB = (uint32_t)__cvta_generic_to_shared(Bs);
    const int alm = lane & 15, alh = lane >> 4;           // A: 16 rows x k-half
    const int blm = lane & 7,  blh = (lane >> 3) & 1;     // B: 8 rows x k-half (lanes 0-15)
    const uint32_t aBase = sA + (((wm * 64 + alm) * SPAD + alh * 4) << 2);
    const uint32_t bBase = sB + (((wn * 32 + blm) * SPAD + blh * 4) << 2);

    float4 acc[4][4];
#pragma unroll
    for (int i = 0; i < 4; ++i)
#pragma unroll
        for (int j = 0; j < 4; ++j) acc[i][j] = make_float4(0.f, 0.f, 0.f, 0.f);

    // Prologue: stage 0
    {
        float4 pa0 = make_float4(0.f, 0.f, 0.f, 0.f), pa1 = pa0;
        if (av0) pa0 = *(const float4*)ap0;
        if (av1) pa1 = *(const float4*)ap1;
        float4 pb0 = *(const float4*)bp0;
        float4 pb1 = *(const float4*)bp1;
        if (SRC == 0) { pa0 = cvt4(pa0); pa1 = cvt4(pa1); }
        *(float4*)&As[0][ar0 * SPAD + ak] = pa0;
        *(float4*)&As[0][ar1 * SPAD + ak] = pa1;
        *(float4*)&Bs[0][ar0 * SPAD + ak] = cvt4(pb0);
        *(float4*)&Bs[0][ar1 * SPAD + ak] = cvt4(pb1);
    }
    __syncthreads();

    const int KT = KD / BKT;
    int buf = 0;
#pragma unroll 1
    for (int kt = 0; kt < KT; ++kt) {
        float4 na0, na1, nb0, nb1;
        const bool more = (kt + 1) < KT;
        if (more) {
            const int ko = (kt + 1) * BKT;
            na0 = make_float4(0.f, 0.f, 0.f, 0.f); na1 = na0;
            if (av0) na0 = *(const float4*)(ap0 + ko);
            if (av1) na1 = *(const float4*)(ap1 + ko);
            nb0 = *(const float4*)(bp0 + ko);
            nb1 = *(const float4*)(bp1 + ko);
        }

        const uint32_t aS = aBase + (uint32_t)buf * ABYTES;
        const uint32_t bS = bBase + (uint32_t)buf * BBYTES;
#pragma unroll
        for (int ks = 0; ks < BKT; ks += 8) {
            uint32_t af[4][4], bf[4][2];
#pragma unroll
            for (int mt = 0; mt < 4; ++mt)
                ldsm_x4(af[mt], aS + (uint32_t)(mt * 16 * SPAD + ks) * 4);
#pragma unroll
            for (int nt = 0; nt < 4; ++nt)
                ldsm_x2(bf[nt], bS + (uint32_t)(nt * 8 * SPAD + ks) * 4);
#pragma unroll
            for (int mt = 0; mt < 4; ++mt)
#pragma unroll
                for (int nt = 0; nt < 4; ++nt)
                    mma8(acc[mt][nt], af[mt], bf[nt]);
        }

        if (more) {
            const int nb = buf ^ 1;
            if (SRC == 0) { na0 = cvt4(na0); na1 = cvt4(na1); }
            *(float4*)&As[nb][ar0 * SPAD + ak] = na0;
            *(float4*)&As[nb][ar1 * SPAD + ak] = na1;
            *(float4*)&Bs[nb][ar0 * SPAD + ak] = cvt4(nb0);
            *(float4*)&Bs[nb][ar1 * SPAD + ak] = cvt4(nb1);
        }
        __syncthreads();
        buf ^= 1;
    }

    // Epilogue
#pragma unroll
    for (int mt = 0; mt < 4; ++mt) {
        const int r0 = row0 + wm * 64 + mt * 16 + grp;
        const int r1 = r0 + 8;
#pragma unroll
        for (int nt = 0; nt < 4; ++nt) {
            const int c = col0 + wn * 32 + nt * 8 + tig * 2;
            float4 v = acc[mt][nt];
            if (OUT == 0) {
                if (r0 < cnt) *(float2*)&g_gbuf[(size_t)(e * CAP + r0) * NDIM + c] = make_float2(v.x, v.y);
                if (r1 < cnt) *(float2*)&g_gbuf[(size_t)(e * CAP + r1) * NDIM + c] = make_float2(v.z, v.w);
            } else if (OUT == 1) {
                if (r0 < cnt) {
                    const size_t o = (size_t)(e * CAP + r0) * NDIM + c;
                    float2 g = *(const float2*)&g_gbuf[o];
                    *(float2*)&g_act[o] = make_float2(actf(g.x, v.x), actf(g.y, v.y));
                }
                if (r1 < cnt) {
                    const size_t o = (size_t)(e * CAP + r1) * NDIM + c;
                    float2 g = *(const float2*)&g_gbuf[o];
                    *(float2*)&g_act[o] = make_float2(actf(g.x, v.z), actf(g.y, v.w));
                }
            } else {
                if (r0 < cnt) *(float2*)&g_dbuf[(size_t)(e * CAP + r0) * KDIM + c] = make_float2(v.x, v.y);
                if (r1 < cnt) *(float2*)&g_dbuf[(size_t)(e * CAP + r1) * KDIM + c] = make_float2(v.z, v.w);
            }
        }
    }
}

// ---------------- combine ----------------
__global__ void k_combine(const float* __restrict__ gate, float* __restrict__ out) {
    const int t = blockIdx.x;
    const int p0 = g_posmap[2 * t];
    const int p1 = g_posmap[2 * t + 1];
    const float g0 = gate[2 * t];
    const float g1 = gate[2 * t + 1];
    const float4* d0 = (const float4*)(g_dbuf + (size_t)p0 * KDIM);
    const float4* d1 = (const float4*)(g_dbuf + (size_t)p1 * KDIM);
    float4* o = (float4*)(out + (size_t)t * KDIM);
    for (int i = threadIdx.x; i < KDIM / 4; i += blockDim.x) {
        float4 a = d0[i];
        float4 b = d1[i];
        o[i] = make_float4(g0 * a.x + g1 * b.x, g0 * a.y + g1 * b.y,
                           g0 * a.z + g1 * b.z, g0 * a.w + g1 * b.w);
    }
}

extern "C" void kernel_launch(void* const* d_in, const int* in_sizes, int n_in,
                              void* d_out, int out_size) {
    (void)in_sizes; (void)n_in; (void)out_size;
    const float* flat_h    = (const float*)d_in[0];
    const int*   flat_idx  = (const int*)  d_in[1];
    const float* flat_gate = (const float*)d_in[2];
    const float* gate_w    = (const float*)d_in[3];
    const float* up_w      = (const float*)d_in[4];
    const float* down_w    = (const float*)d_in[5];
    float* out = (float*)d_out;

    k_route<<<1, 256>>>(flat_idx);

    dim3 grid1(NDIM / BN, CAP / BM, NEXP);   // (11, 8, 8)
    k_gemm<KDIM, 0, 0><<<grid1, NTHR>>>(flat_h, gate_w);   // gate pre-act
    k_gemm<KDIM, 0, 1><<<grid1, NTHR>>>(flat_h, up_w);     // up + fused SwiGLU

    dim3 grid2(KDIM / BN, CAP / BM, NEXP);   // (16, 8, 8)
    k_gemm<NDIM, 1, 2><<<grid2, NTHR>>>(nullptr, down_w);  // down

    k_combine<<<MTOK, 256>>>(flat_gate, out);
}

// round 8
// speedup vs baseline: 1.9739x; 1.1069x over previous
#include <cuda_runtime.h>
#include <cstdint>
#include <math.h>

// ---------------- problem constants ----------------
#define MTOK 2048
#define KDIM 2048
#define NDIM 1408
#define NEXP 8
#define CAP  1024
#define RROWS 4096
#define ECAP  8192

// ---------------- tiling ----------------
#define BM 128
#define BN1 128              // mlp1: 128 cols of gate AND up
#define BN2 256              // mlp2: 256 cols
#define BKT 16
#define SPAD 20              // 80-byte row stride: LDSM row addresses hit all 32 banks
#define NTHR 256
#define TSTAGE (BM * SPAD)               // floats per 128-row stage
#define SMEM_BYTES (6 * TSTAGE * 4)      // 61440 (both kernels)

// ---------------- scratch ----------------
__device__ __align__(16) float g_act[(size_t)ECAP * NDIM];  // SwiGLU out (tf32-rounded); rows>=cnt stay 0
__device__ __align__(16) float g_dbuf[(size_t)ECAP * KDIM];
__device__ int g_cnt[NEXP];
__device__ int g_rowtok[ECAP];
__device__ int g_posmap[RROWS];

// ---------------- helpers ----------------
__device__ __forceinline__ float to_tf32(float x) {
    float r;
    asm("cvt.rna.tf32.f32 %0, %1;" : "=f"(r) : "f"(x));
    return r;
}
__device__ __forceinline__ float4 cvt4(float4 v) {
    v.x = to_tf32(v.x); v.y = to_tf32(v.y);
    v.z = to_tf32(v.z); v.w = to_tf32(v.w);
    return v;
}
__device__ __forceinline__ void mma8(float4& d, const uint32_t* a, const uint32_t* b) {
    asm volatile(
        "mma.sync.aligned.m16n8k8.row.col.f32.tf32.tf32.f32 "
        "{%0,%1,%2,%3}, {%4,%5,%6,%7}, {%8,%9}, {%0,%1,%2,%3};\n"
        : "+f"(d.x), "+f"(d.y), "+f"(d.z), "+f"(d.w)
        : "r"(a[0]), "r"(a[1]), "r"(a[2]), "r"(a[3]), "r"(b[0]), "r"(b[1]));
}
__device__ __forceinline__ void ldsm_x4(uint32_t* a, uint32_t addr) {
    asm volatile("ldmatrix.sync.aligned.m8n8.x4.shared.b16 {%0,%1,%2,%3}, [%4];"
                 : "=r"(a[0]), "=r"(a[1]), "=r"(a[2]), "=r"(a[3]) : "r"(addr));
}
__device__ __forceinline__ void ldsm_x2(uint32_t* b, uint32_t addr) {
    asm volatile("ldmatrix.sync.aligned.m8n8.x2.shared.b16 {%0,%1}, [%2];"
                 : "=r"(b[0]), "=r"(b[1]) : "r"(addr));
}

// ---------------- routing ----------------
__global__ void k_route(const int* __restrict__ idx) {
    __shared__ int sc[NEXP];
    const int tid = threadIdx.x;
    if (tid < NEXP) sc[tid] = 0;
    __syncthreads();
    for (int r = tid; r < RROWS; r += blockDim.x) {
        int e = idx[r];
        int slot = atomicAdd(&sc[e], 1);
        if (slot < CAP) {
            int p = e * CAP + slot;
            g_rowtok[p] = r >> 1;
            g_posmap[r] = p;
        } else {
            g_posmap[r] = e * CAP;
        }
    }
    __syncthreads();
    if (tid < NEXP) g_cnt[tid] = min(sc[tid], CAP);
}

__device__ __forceinline__ float actf(float g, float u) {
    g = fminf(g, 10.0f);
    u = fminf(fmaxf(u, -10.0f), 10.0f);
    float s = g / (1.0f + expf(-g));
    return to_tf32(s * u);
}

// ---------------------------------------------------------------------------
// k_mlp1: fused gate+up GEMM, CTA 128 x 128 (both outputs), 8 warps 2(M)x4(N),
// warp tile 64x32 per output, A fragments reused for both B matrices.
// SwiGLU applied in registers -> g_act (tf32-rounded).
// ---------------------------------------------------------------------------
__global__ __launch_bounds__(NTHR, 1)
void k_mlp1(const float* __restrict__ H, const float* __restrict__ Wg,
            const float* __restrict__ Wu) {
    extern __shared__ __align__(16) float smem[];
    float* As  = smem;                // 2 stages
    float* Bgs = smem + 2 * TSTAGE;   // 2 stages
    float* Bus = smem + 4 * TSTAGE;   // 2 stages

    const int e    = blockIdx.z;
    const int cnt  = g_cnt[e];
    const int row0 = blockIdx.y * BM;
    if (row0 >= cnt) return;
    const int col0 = blockIdx.x * BN1;

    const int tid  = threadIdx.x;
    const int lane = tid & 31;
    const int warp = tid >> 5;
    const int wm   = warp >> 2;
    const int wn   = warp & 3;
    const int grp  = lane >> 2;
    const int tig  = lane & 3;

    const int ar0 = tid >> 2;            // 0..63
    const int ak  = (tid & 3) * 4;
    const int ar1 = ar0 + 64;

    const bool av0 = (row0 + ar0) < cnt;
    const bool av1 = (row0 + ar1) < cnt;
    int t0 = av0 ? g_rowtok[e * CAP + row0 + ar0] : 0;
    int t1 = av1 ? g_rowtok[e * CAP + row0 + ar1] : 0;
    const float* ap0 = H + (size_t)t0 * KDIM + ak;
    const float* ap1 = H + (size_t)t1 * KDIM + ak;
    const size_t wbo = (size_t)e * ((size_t)NDIM * KDIM);
    const float* bg0 = Wg + wbo + (size_t)(col0 + ar0) * KDIM + ak;
    const float* bg1 = Wg + wbo + (size_t)(col0 + ar1) * KDIM + ak;
    const float* bu0 = Wu + wbo + (size_t)(col0 + ar0) * KDIM + ak;
    const float* bu1 = Wu + wbo + (size_t)(col0 + ar1) * KDIM + ak;

    const uint32_t sA  = (uint32_t)__cvta_generic_to_shared(As);
    const uint32_t sBg = (uint32_t)__cvta_generic_to_shared(Bgs);
    const uint32_t sBu = (uint32_t)__cvta_generic_to_shared(Bus);
    const int alm = lane & 15, alh = lane >> 4;
    const int blm = lane & 7,  blh = (lane >> 3) & 1;
    const uint32_t aBase  = sA  + (((wm * 64 + alm) * SPAD + alh * 4) << 2);
    const uint32_t bgBase = sBg + (((wn * 32 + blm) * SPAD + blh * 4) << 2);
    const uint32_t buBase = sBu + (((wn * 32 + blm) * SPAD + blh * 4) << 2);

    float4 accg[4][4], accu[4][4];
#pragma unroll
    for (int i = 0; i < 4; ++i)
#pragma unroll
        for (int j = 0; j < 4; ++j) {
            accg[i][j] = make_float4(0.f, 0.f, 0.f, 0.f);
            accu[i][j] = make_float4(0.f, 0.f, 0.f, 0.f);
        }

    // Prologue
    {
        float4 pa0 = make_float4(0.f, 0.f, 0.f, 0.f), pa1 = pa0;
        if (av0) pa0 = *(const float4*)ap0;
        if (av1) pa1 = *(const float4*)ap1;
        *(float4*)&As[ar0 * SPAD + ak] = cvt4(pa0);
        *(float4*)&As[ar1 * SPAD + ak] = cvt4(pa1);
        *(float4*)&Bgs[ar0 * SPAD + ak] = cvt4(*(const float4*)bg0);
        *(float4*)&Bgs[ar1 * SPAD + ak] = cvt4(*(const float4*)bg1);
        *(float4*)&Bus[ar0 * SPAD + ak] = cvt4(*(const float4*)bu0);
        *(float4*)&Bus[ar1 * SPAD + ak] = cvt4(*(const float4*)bu1);
    }
    __syncthreads();

    const int KT = KDIM / BKT;   // 128
    int buf = 0;
#pragma unroll 1
    for (int kt = 0; kt < KT; ++kt) {
        float4 na0, na1, ng0, ng1, nu0, nu1;
        const bool more = (kt + 1) < KT;
        if (more) {
            const int ko = (kt + 1) * BKT;
            na0 = make_float4(0.f, 0.f, 0.f, 0.f); na1 = na0;
            if (av0) na0 = *(const float4*)(ap0 + ko);
            if (av1) na1 = *(const float4*)(ap1 + ko);
            ng0 = *(const float4*)(bg0 + ko);
            ng1 = *(const float4*)(bg1 + ko);
            nu0 = *(const float4*)(bu0 + ko);
            nu1 = *(const float4*)(bu1 + ko);
        }

        const uint32_t aS  = aBase  + (uint32_t)buf * (TSTAGE * 4);
        const uint32_t bgS = bgBase + (uint32_t)buf * (TSTAGE * 4);
        const uint32_t buS = buBase + (uint32_t)buf * (TSTAGE * 4);
#pragma unroll
        for (int ks = 0; ks < BKT; ks += 8) {
            uint32_t af[4][4], bgf[4][2], buf_[4][2];
#pragma unroll
            for (int mt = 0; mt < 4; ++mt)
                ldsm_x4(af[mt], aS + (uint32_t)(mt * 16 * SPAD + ks) * 4);
#pragma unroll
            for (int nt = 0; nt < 4; ++nt) {
                ldsm_x2(bgf[nt], bgS + (uint32_t)(nt * 8 * SPAD + ks) * 4);
                ldsm_x2(buf_[nt], buS + (uint32_t)(nt * 8 * SPAD + ks) * 4);
            }
#pragma unroll
            for (int mt = 0; mt < 4; ++mt)
#pragma unroll
                for (int nt = 0; nt < 4; ++nt) {
                    mma8(accg[mt][nt], af[mt], bgf[nt]);
                    mma8(accu[mt][nt], af[mt], buf_[nt]);
                }
        }

        if (more) {
            const int nb = buf ^ 1;
            *(float4*)&As[nb * TSTAGE + ar0 * SPAD + ak] = cvt4(na0);
            *(float4*)&As[nb * TSTAGE + ar1 * SPAD + ak] = cvt4(na1);
            *(float4*)&Bgs[nb * TSTAGE + ar0 * SPAD + ak] = cvt4(ng0);
            *(float4*)&Bgs[nb * TSTAGE + ar1 * SPAD + ak] = cvt4(ng1);
            *(float4*)&Bus[nb * TSTAGE + ar0 * SPAD + ak] = cvt4(nu0);
            *(float4*)&Bus[nb * TSTAGE + ar1 * SPAD + ak] = cvt4(nu1);
        }
        __syncthreads();
        buf ^= 1;
    }

    // SwiGLU epilogue straight from registers
#pragma unroll
    for (int mt = 0; mt < 4; ++mt) {
        const int r0 = row0 + wm * 64 + mt * 16 + grp;
        const int r1 = r0 + 8;
#pragma unroll
        for (int nt = 0; nt < 4; ++nt) {
            const int c = col0 + wn * 32 + nt * 8 + tig * 2;
            float4 g = accg[mt][nt];
            float4 u = accu[mt][nt];
            if (r0 < cnt)
                *(float2*)&g_act[(size_t)(e * CAP + r0) * NDIM + c] =
                    make_float2(actf(g.x, u.x), actf(g.y, u.y));
            if (r1 < cnt)
                *(float2*)&g_act[(size_t)(e * CAP + r1) * NDIM + c] =
                    make_float2(actf(g.z, u.z), actf(g.w, u.w));
        }
    }
}

// ---------------------------------------------------------------------------
// k_mlp2: down-projection, CTA 128 x 256, 8 warps 2(M)x4(N), warp tile 64x64.
// A = g_act (pre-rounded tf32, rows>=cnt zero), B = down_weight.
// ---------------------------------------------------------------------------
__global__ __launch_bounds__(NTHR, 1)
void k_mlp2(const float* __restrict__ W) {
    extern __shared__ __align__(16) float smem[];
    float* As = smem;                 // 2 stages of 128 rows
    float* Bs = smem + 2 * TSTAGE;    // 2 stages of 256 rows

    const int e    = blockIdx.z;
    const int cnt  = g_cnt[e];
    const int row0 = blockIdx.y * BM;
    if (row0 >= cnt) return;
    const int col0 = blockIdx.x * BN2;

    const int tid  = threadIdx.x;
    const int lane = tid & 31;
    const int warp = tid >> 5;
    const int wm   = warp >> 2;
    const int wn   = warp & 3;
    const int grp  = lane >> 2;
    const int tig  = lane & 3;

    const int ar0 = tid >> 2;            // 0..63
    const int ak  = (tid & 3) * 4;
    const int ar1 = ar0 + 64;

    const float* ap0 = g_act + (size_t)(e * CAP + row0 + ar0) * NDIM + ak;
    const float* ap1 = g_act + (size_t)(e * CAP + row0 + ar1) * NDIM + ak;
    const size_t wbo = (size_t)e * ((size_t)NDIM * KDIM);
    const float* bp[4];
#pragma unroll
    for (int j = 0; j < 4; ++j)
        bp[j] = W + wbo + (size_t)(col0 + ar0 + j * 64) * NDIM + ak;

    const uint32_t sA = (uint32_t)__cvta_generic_to_shared(As);
    const uint32_t sB = (uint32_t)__cvta_generic_to_shared(Bs);
    const int alm = lane & 15, alh = lane >> 4;
    const int blm = lane & 7,  blh = (lane >> 3) & 1;
    const uint32_t aBase = sA + (((wm * 64 + alm) * SPAD + alh * 4) << 2);
    const uint32_t bBase = sB + (((wn * 64 + blm) * SPAD + blh * 4) << 2);

    float4 acc[4][8];
#pragma unroll
    for (int i = 0; i < 4; ++i)
#pragma unroll
        for (int j = 0; j < 8; ++j) acc[i][j] = make_float4(0.f, 0.f, 0.f, 0.f);

    // Prologue
    {
        *(float4*)&As[ar0 * SPAD + ak] = *(const float4*)ap0;
        *(float4*)&As[ar1 * SPAD + ak] = *(const float4*)ap1;
#pragma unroll
        for (int j = 0; j < 4; ++j)
            *(float4*)&Bs[(ar0 + j * 64) * SPAD + ak] = cvt4(*(const float4*)bp[j]);
    }
    __syncthreads();

    const int KT = NDIM / BKT;   // 88
    int buf = 0;
#pragma unroll 1
    for (int kt = 0; kt < KT; ++kt) {
        float4 na0, na1, nb[4];
        const bool more = (kt + 1) < KT;
        if (more) {
            const int ko = (kt + 1) * BKT;
            na0 = *(const float4*)(ap0 + ko);
            na1 = *(const float4*)(ap1 + ko);
#pragma unroll
            for (int j = 0; j < 4; ++j) nb[j] = *(const float4*)(bp[j] + ko);
        }

        const uint32_t aS = aBase + (uint32_t)buf * (TSTAGE * 4);
        const uint32_t bS = bBase + (uint32_t)buf * (2 * TSTAGE * 4);
#pragma unroll
        for (int ks = 0; ks < BKT; ks += 8) {
            uint32_t af[4][4], bf[8][2];
#pragma unroll
            for (int mt = 0; mt < 4; ++mt)
                ldsm_x4(af[mt], aS + (uint32_t)(mt * 16 * SPAD + ks) * 4);
#pragma unroll
            for (int nt = 0; nt < 8; ++nt)
                ldsm_x2(bf[nt], bS + (uint32_t)(nt * 8 * SPAD + ks) * 4);
#pragma unroll
            for (int mt = 0; mt < 4; ++mt)
#pragma unroll
                for (int nt = 0; nt < 8; ++nt)
                    mma8(acc[mt][nt], af[mt], bf[nt]);
        }

        if (more) {
            const int nbuf = buf ^ 1;
            *(float4*)&As[nbuf * TSTAGE + ar0 * SPAD + ak] = na0;
            *(float4*)&As[nbuf * TSTAGE + ar1 * SPAD + ak] = na1;
#pragma unroll
            for (int j = 0; j < 4; ++j)
                *(float4*)&Bs[nbuf * 2 * TSTAGE + (ar0 + j * 64) * SPAD + ak] = cvt4(nb[j]);
        }
        __syncthreads();
        buf ^= 1;
    }

#pragma unroll
    for (int mt = 0; mt < 4; ++mt) {
        const int r0 = row0 + wm * 64 + mt * 16 + grp;
        const int r1 = r0 + 8;
#pragma unroll
        for (int nt = 0; nt < 8; ++nt) {
            const int c = col0 + wn * 64 + nt * 8 + tig * 2;
            float4 v = acc[mt][nt];
            if (r0 < cnt) *(float2*)&g_dbuf[(size_t)(e * CAP + r0) * KDIM + c] = make_float2(v.x, v.y);
            if (r1 < cnt) *(float2*)&g_dbuf[(size_t)(e * CAP + r1) * KDIM + c] = make_float2(v.z, v.w);
        }
    }
}

// ---------------- combine ----------------
__global__ void k_combine(const float* __restrict__ gate, float* __restrict__ out) {
    const int t = blockIdx.x;
    const int p0 = g_posmap[2 * t];
    const int p1 = g_posmap[2 * t + 1];
    const float g0 = gate[2 * t];
    const float g1 = gate[2 * t + 1];
    const float4* d0 = (const float4*)(g_dbuf + (size_t)p0 * KDIM);
    const float4* d1 = (const float4*)(g_dbuf + (size_t)p1 * KDIM);
    float4* o = (float4*)(out + (size_t)t * KDIM);
    for (int i = threadIdx.x; i < KDIM / 4; i += blockDim.x) {
        float4 a = d0[i];
        float4 b = d1[i];
        o[i] = make_float4(g0 * a.x + g1 * b.x, g0 * a.y + g1 * b.y,
                           g0 * a.z + g1 * b.z, g0 * a.w + g1 * b.w);
    }
}

extern "C" void kernel_launch(void* const* d_in, const int* in_sizes, int n_in,
                              void* d_out, int out_size) {
    (void)in_sizes; (void)n_in; (void)out_size;
    const float* flat_h    = (const float*)d_in[0];
    const int*   flat_idx  = (const int*)  d_in[1];
    const float* flat_gate = (const float*)d_in[2];
    const float* gate_w    = (const float*)d_in[3];
    const float* up_w      = (const float*)d_in[4];
    const float* down_w    = (const float*)d_in[5];
    float* out = (float*)d_out;

    cudaFuncSetAttribute(k_mlp1, cudaFuncAttributeMaxDynamicSharedMemorySize, SMEM_BYTES);
    cudaFuncSetAttribute(k_mlp2, cudaFuncAttributeMaxDynamicSharedMemorySize, SMEM_BYTES);

    k_route<<<1, 256>>>(flat_idx);

    dim3 grid1(NDIM / BN1, CAP / BM, NEXP);   // (11, 8, 8)
    k_mlp1<<<grid1, NTHR, SMEM_BYTES>>>(flat_h, gate_w, up_w);

    dim3 grid2(KDIM / BN2, CAP / BM, NEXP);   // (8, 8, 8)
    k_mlp2<<<grid2, NTHR, SMEM_BYTES>>>(down_w);

    k_combine<<<MTOK, 256>>>(flat_gate, out);
}